// round 11
// baseline (speedup 1.0000x reference)
#include <cuda_runtime.h>
#include <cuda_bf16.h>
#include <cstdint>

#define FULL 0xffffffffu
#define EPS 1e-8f
#define WARPS_PER_BLOCK 8
#define THREADS 256
#define BLOCKS_PER_SM 6
#define NUM_SMS 148
#define N_MAX 100000
#define M_MAX 50000

// Quantization: x,y -> 5 bits, z -> 6 bits over [-4.75, 4.75]
#define QOFF   4.75f
#define QSC_XY (31.0f / 9.5f)
#define QSC_Z  (63.0f / 9.5f)
#define QIV_XY (9.5f / 31.0f)
#define QIV_Z  (9.5f / 63.0f)
// half-steps: hxy=0.15323, hz=0.07540 ; ||h||=0.22943 ; (1+||h||)^2=1.5115
#define FILT_THRESH 1.5120f

// Packed scratch (filled by prepass).
__device__ float4 g_points4[N_MAX];
__device__ unsigned short g_quant[N_MAX];   // 200 KB -> L1-resident prefilter
__device__ float4 g_q4[M_MAX];

__device__ __forceinline__ float fast_sqrt(float x) {
    float r;
    asm("sqrt.approx.ftz.f32 %0, %1;" : "=f"(r) : "f"(x));
    return r;
}

__global__ void pack_kernel(const float* __restrict__ points, int N,
                            const float* __restrict__ q_coords, int M) {
    int i = blockIdx.x * blockDim.x + threadIdx.x;
    if (i < N) {
        float x = points[3 * i + 0];
        float y = points[3 * i + 1];
        float z = points[3 * i + 2];
        g_points4[i] = make_float4(x, y, z, 0.0f);
        float fx = (x + QOFF) * QSC_XY;
        float fy = (y + QOFF) * QSC_XY;
        float fz = (z + QOFF) * QSC_Z;
        unsigned short qv;
        if (fx < 0.f || fx > 31.f || fy < 0.f || fy > 31.f || fz < 0.f || fz > 63.f) {
            qv = 0xFFFFu;                     // out of range: force-pass sentinel
        } else {
            int ix = __float2int_rn(fx);
            int iy = __float2int_rn(fy);
            int iz = __float2int_rn(fz);
            qv = (unsigned short)((ix << 11) | (iy << 6) | iz);
        }
        g_quant[i] = qv;
    }
    if (i < M)
        g_q4[i] = make_float4(q_coords[3 * i + 0], q_coords[3 * i + 1],
                              q_coords[3 * i + 2], 0.0f);
}

// Conservative prefilter: true iff point COULD satisfy d2<=1 (never false-negative).
__device__ __forceinline__ bool prefilter(unsigned short qv, float4 q) {
    if (qv == 0xFFFFu) return true;
    int ux = (qv >> 11) & 31;
    int uy = (qv >> 6) & 31;
    int uz = qv & 63;
    float dx = fmaf((float)ux, QIV_XY, -QOFF) - q.x;
    float dy = fmaf((float)uy, QIV_XY, -QOFF) - q.y;
    float dz = fmaf((float)uz, QIV_Z,  -QOFF) - q.z;
    float d2q = fmaf(dx, dx, fmaf(dy, dy, dz * dz));
    return d2q <= FILT_THRESH;
}

__global__ __launch_bounds__(THREADS, BLOCKS_PER_SM)
void gib_kernel(const int* __restrict__ support_idxs,
                const float* __restrict__ cy_radius,
                const float* __restrict__ disk_radius,
                const float* __restrict__ disk_width,
                const float* __restrict__ cone_radius,
                const float* __restrict__ cone_inc,
                const float* __restrict__ ellip_radii,
                const float* __restrict__ lambdas,
                float* __restrict__ out,
                int M, int P /* number of query pairs */)
{
    __shared__ float4 s_coef[32];
    __shared__ float  s_inc[32];
    __shared__ float  s_lamT[16][36];                 // transposed, padded, /K folded
    __shared__ float4 s_surv[WARPS_PER_BLOCK][2][32]; // compacted survivors (+acc alias)

    int tid = threadIdx.x;

    if (tid < 32) {
        int kind = tid >> 3;
        int g    = tid & 7;
        float a = 0.f, b = 0.f, c = 0.f, e = 0.f, inc = 0.f;
        if (kind == 0) {                 // cylinder
            float r = cy_radius[g];
            float v = -0.5f / (r * r + EPS);
            a = v; b = v;
        } else if (kind == 1) {          // cone
            float r = cone_radius[g];
            e = -0.5f / (r * r + EPS);
            inc = cone_inc[g];
        } else if (kind == 2) {          // disk
            float r = disk_radius[g];
            float w = disk_width[g];
            float v = -0.5f / (r * r + EPS);
            a = v; b = v;
            c = -0.5f / (w * w + EPS);
        } else {                         // ellipsoid
            float ex = ellip_radii[g * 3 + 0];
            float ey = ellip_radii[g * 3 + 1];
            float ez = ellip_radii[g * 3 + 2];
            a = -0.5f / (ex * ex + EPS);
            b = -0.5f / (ey * ey + EPS);
            c = -0.5f / (ez * ez + EPS);
        }
        s_coef[tid] = make_float4(a, b, c, e);
        s_inc[tid] = inc;
    }
    for (int i = tid; i < 32 * 16; i += THREADS) {
        int j = i >> 4, o = i & 15;
        s_lamT[o][j] = lambdas[i] * (1.0f / 32.0f);   // fold masked-mean 1/K
    }
    __syncthreads();

    int lane = tid & 31;
    int wid  = tid >> 5;
    unsigned ltmask = (1u << lane) - 1u;

    float4 cf  = s_coef[lane];
    float  inc = s_inc[lane];

    int gw     = blockIdx.x * WARPS_PER_BLOCK + wid;
    int stride = gridDim.x * WARPS_PER_BLOCK;

    int p = gw;
    if (p >= P) return;

    // ---- Prologue: idx + quant for pair p, idx for pair p+stride ----
    int m0 = 2 * p;
    int m1 = min(2 * p + 1, M - 1);
    int ia = __ldcg(&support_idxs[m0 * 32 + lane]);
    int ib = __ldcg(&support_idxs[m1 * 32 + lane]);
    unsigned short qa = g_quant[ia];       // L1-resident
    unsigned short qb = g_quant[ib];

    int pn = p + stride;
    int ian = ia, ibn = ib;
    if (pn < P) {
        ian = __ldcg(&support_idxs[(2 * pn) * 32 + lane]);
        ibn = __ldcg(&support_idxs[min(2 * pn + 1, M - 1) * 32 + lane]);
    }

    while (p < P) {
        // ---- Prefetch quant for next pair, idx for pair after ----
        unsigned short qan = qa, qbn = qb;
        if (pn < P) {
            qan = g_quant[ian];
            qbn = g_quant[ibn];
        }
        int pnn = pn + stride;
        int ian2 = ian, ibn2 = ibn;
        if (pnn < P) {
            ian2 = __ldcg(&support_idxs[(2 * pnn) * 32 + lane]);
            ibn2 = __ldcg(&support_idxs[min(2 * pnn + 1, M - 1) * 32 + lane]);
        }

        float4 qv0 = __ldcg(&g_q4[m0]);
        float4 qv1 = __ldcg(&g_q4[m1]);

        // ---- Stage 1: conservative quantized filter (quant in regs) ----
        bool passA = prefilter(qa, qv0);
        bool passB = prefilter(qb, qv1);

        // ---- Stage 2: exact fetch+test only for passing lanes (~14%) ----
        float x2a = 0.f, y2a = 0.f, za = 0.f, rxya = 0.f, d2a = 9e9f;
        float x2b = 0.f, y2b = 0.f, zb = 0.f, rxyb = 0.f, d2b = 9e9f;
        if (passA) {
            float4 pa = __ldcg(&g_points4[ia]);
            float xa = pa.x - qv0.x, ya = pa.y - qv0.y;
            za = pa.z - qv0.z;
            x2a = xa * xa; y2a = ya * ya;
            float xy2a = x2a + y2a;
            d2a = xy2a + za * za;
            rxya = fast_sqrt(xy2a + EPS);
        }
        if (passB) {
            float4 pb = __ldcg(&g_points4[ib]);
            float xb = pb.x - qv1.x, yb = pb.y - qv1.y;
            zb = pb.z - qv1.z;
            x2b = xb * xb; y2b = yb * yb;
            float xy2b = x2b + y2b;
            d2b = xy2b + zb * zb;
            rxyb = fast_sqrt(xy2b + EPS);
        }

        bool alive0 = (d2a <= 1.0f);
        bool alive1 = (d2b <= 1.0f) && (m1 == 2 * p + 1);
        unsigned b0 = __ballot_sync(FULL, alive0);
        unsigned b1 = __ballot_sync(FULL, alive1);
        int n0 = __popc(b0);
        int n1 = __popc(b1);

        float4* surv = &s_surv[wid][0][0];   // slots [0..31]=q0, [32..63]=q1
        if (alive0) surv[__popc(b0 & ltmask)]      = make_float4(x2a, y2a, za, rxya);
        if (alive1) surv[32 + __popc(b1 & ltmask)] = make_float4(x2b, y2b, zb, rxyb);
        __syncwarp();

        float acc0 = 0.0f, acc1 = 0.0f;
        int nmax = max(n0, n1);
        #pragma unroll 2
        for (int j = 0; j < nmax; j++) {
            if (j < n0) {
                float4 v = surv[j];
                float dd = fmaf(-inc, v.z, v.w);
                float t = fmaf(cf.x, v.x,
                          fmaf(cf.y, v.y,
                          fmaf(cf.z, v.z * v.z, (cf.w * dd) * dd)));
                acc0 += __expf(t);
            }
            if (j < n1) {
                float4 v = surv[32 + j];
                float dd = fmaf(-inc, v.z, v.w);
                float t = fmaf(cf.x, v.x,
                          fmaf(cf.y, v.y,
                          fmaf(cf.z, v.z * v.z, (cf.w * dd) * dd)));
                acc1 += __expf(t);
            }
        }
        __syncwarp();

        // Stage accumulators (alias survivor region — survivor data now dead).
        float* accp = (float*)surv;
        accp[lane]      = acc0;
        accp[32 + lane] = acc1;
        __syncwarp();

        // Epilogue: lanes 0-15 -> q0, lanes 16-31 -> q1; two partial chains.
        int qsel = lane >> 4;
        int o    = lane & 15;
        int mst  = qsel ? (2 * p + 1) : m0;
        if (mst < M) {
            const float* arow = accp + qsel * 32;
            float ot0 = 0.0f, ot1 = 0.0f;
            #pragma unroll
            for (int j = 0; j < 16; j += 4) {
                float4 lamA = *(const float4*)&s_lamT[o][j];
                float4 aA   = *(const float4*)&arow[j];
                ot0 = fmaf(aA.x, lamA.x,
                      fmaf(aA.y, lamA.y,
                      fmaf(aA.z, lamA.z,
                      fmaf(aA.w, lamA.w, ot0))));
                float4 lamB = *(const float4*)&s_lamT[o][j + 16];
                float4 aB   = *(const float4*)&arow[j + 16];
                ot1 = fmaf(aB.x, lamB.x,
                      fmaf(aB.y, lamB.y,
                      fmaf(aB.z, lamB.z,
                      fmaf(aB.w, lamB.w, ot1))));
            }
            out[mst * 16 + o] = ot0 + ot1;
        }
        __syncwarp();

        // ---- Rotate ----
        p = pn; pn = pnn;
        m0 = 2 * p;
        m1 = min(2 * p + 1, M - 1);
        ia = ian; ib = ibn;
        ian = ian2; ibn = ibn2;
        qa = qan; qb = qbn;
    }
}

extern "C" void kernel_launch(void* const* d_in, const int* in_sizes, int n_in,
                              void* d_out, int out_size) {
    const float* points       = (const float*)d_in[0];
    const float* q_coords     = (const float*)d_in[1];
    const int*   support_idxs = (const int*)  d_in[2];
    const float* cy_radius    = (const float*)d_in[3];
    const float* disk_radius  = (const float*)d_in[4];
    const float* disk_width   = (const float*)d_in[5];
    const float* cone_radius  = (const float*)d_in[6];
    const float* cone_inc     = (const float*)d_in[7];
    const float* ellip_radii  = (const float*)d_in[8];
    const float* lambdas      = (const float*)d_in[9];
    float* out = (float*)d_out;

    int N = in_sizes[0] / 3;   // points has N*3 elements
    int M = in_sizes[1] / 3;   // q_coords has M*3 elements
    int P = (M + 1) / 2;       // query pairs

    int packN = N > M ? N : M;
    pack_kernel<<<(packN + 255) / 256, 256>>>(points, N, q_coords, M);

    int maxBlocks = NUM_SMS * BLOCKS_PER_SM;
    int needBlocks = (P + WARPS_PER_BLOCK - 1) / WARPS_PER_BLOCK;
    int blocks = needBlocks < maxBlocks ? needBlocks : maxBlocks;
    gib_kernel<<<blocks, THREADS>>>(support_idxs,
                                    cy_radius, disk_radius, disk_width,
                                    cone_radius, cone_inc, ellip_radii,
                                    lambdas, out, M, P);
}